// round 1
// baseline (speedup 1.0000x reference)
#include <cuda_runtime.h>

#define B_  8
#define N_  256
#define DN  64
#define DE  32
#define DC  64
#define DO_ 60

// Scratch (allocation-free rule: __device__ globals). 512 KB each.
__device__ __align__(16) float g_pr [B_*N_*DC];
__device__ __align__(16) float g_psb[B_*N_*DC];

// ---------------------------------------------------------------------------
// Kernel A: per-node precompute.
//   g_pr [b,n,c] = node[b,n,:] @ W_e[32:96 , c]          (receiver term)
//   g_psb[b,n,c] = node[b,n,:] @ W_e[96:160, c] + b_e[c] (sender term + bias)
//   out  [b,n,o] = node[b,n,:] @ W_n[0:64 , o] + b_n[o]  (node part of output)
// ---------------------------------------------------------------------------
__global__ void precompute_kernel(const float* __restrict__ node,
                                  const float* __restrict__ W_e,
                                  const float* __restrict__ b_e,
                                  const float* __restrict__ W_n,
                                  const float* __restrict__ b_n,
                                  float* __restrict__ out) {
    __shared__ float nrow[DN];
    const int bn = blockIdx.x;
    const int c  = threadIdx.x;              // 0..63
    nrow[c] = node[bn*DN + c];
    __syncthreads();

    float accR = 0.f, accS = 0.f, accO = 0.f;
    #pragma unroll 8
    for (int k = 0; k < DN; k++) {
        float nv = nrow[k];
        accR = fmaf(nv, W_e[(DE      + k)*DC + c], accR);
        accS = fmaf(nv, W_e[(DE + DN + k)*DC + c], accS);
        if (c < DO_) accO = fmaf(nv, W_n[k*DO_ + c], accO);
    }
    g_pr [bn*DC + c] = accR;
    g_psb[bn*DC + c] = accS + b_e[c];
    if (c < DO_) out[bn*DO_ + c] = accO + b_n[c];
}

// ---------------------------------------------------------------------------
// Packed f32x2 helpers (FFMA2: 2 FMAs/instr, same rt as scalar FFMA-3reg)
// ---------------------------------------------------------------------------
__device__ __forceinline__ unsigned long long pack2(float a, float b) {
    unsigned long long r;
    asm("mov.b64 %0, {%1,%2};" : "=l"(r) : "f"(a), "f"(b));
    return r;
}
__device__ __forceinline__ unsigned long long fma2(unsigned long long a,
                                                   unsigned long long b,
                                                   unsigned long long c) {
    unsigned long long d;
    asm("fma.rn.f32x2 %0, %1, %2, %3;" : "=l"(d) : "l"(a), "l"(b), "l"(c));
    return d;
}
__device__ __forceinline__ float2 unpack2(unsigned long long v) {
    float2 f;
    asm("mov.b64 {%0,%1}, %2;" : "=f"(f.x), "=f"(f.y) : "l"(v));
    return f;
}

// ---------------------------------------------------------------------------
// Kernel B: one CTA per (b, r).
//   edge_code[s,c] = lrelu(edge_attr[b,r,s,:] @ W_e[0:32,c] + pr[c] + psb[s,c])
//   agg[c]         = sum_s adj[b,r,s] * edge_code[s,c]
//   out[b,r,o]    += agg @ W_n[64:128, o]
// Thread map: c = tid&63 (output channel), sg = tid>>6 (sender group of 64).
// All lanes of a warp share s -> adj branch is warp-uniform, e_sm reads are
// broadcasts, psb_sm reads are conflict-free.
// ---------------------------------------------------------------------------
__global__ void __launch_bounds__(256, 2) edge_kernel(
    const float* __restrict__ edge_attr,
    const float* __restrict__ adj,
    const float* __restrict__ W_e,
    const float* __restrict__ W_n,
    float* __restrict__ out) {

    extern __shared__ float smem[];
    float* e_sm   = smem;                    // 256*32 = 8192
    float* psb_sm = e_sm   + N_*DE;          // 256*64 = 16384
    float* adj_sm = psb_sm + N_*DC;          // 256
    float* pr_sm  = adj_sm + N_;             // 64
    float* red    = pr_sm  + DC;             // 256
    float* aggsm  = red    + 256;            // 64

    const int tid = threadIdx.x;
    const int bn  = blockIdx.x;              // b*N + r
    const int b   = bn >> 8;
    const int c   = tid & 63;
    const int sg  = tid >> 6;

    // --- cooperative loads (all coalesced float4) ---
    const float4* esrc = reinterpret_cast<const float4*>(edge_attr) + (size_t)bn * (N_*DE/4);
    float4* e4 = reinterpret_cast<float4*>(e_sm);
    #pragma unroll
    for (int i = 0; i < (N_*DE/4)/256; i++)          // 8 iters
        e4[tid + i*256] = esrc[tid + i*256];

    const float4* psrc = reinterpret_cast<const float4*>(g_psb) + (size_t)b * (N_*DC/4);
    float4* p4 = reinterpret_cast<float4*>(psb_sm);
    #pragma unroll
    for (int i = 0; i < (N_*DC/4)/256; i++)          // 16 iters
        p4[tid + i*256] = psrc[tid + i*256];

    if (tid < N_/4)
        reinterpret_cast<float4*>(adj_sm)[tid] =
            reinterpret_cast<const float4*>(adj)[(size_t)bn*(N_/4) + tid];
    if (tid < DC) pr_sm[tid] = g_pr[bn*DC + tid];
    __syncthreads();

    // W_e column c (rows 0..31), packed in pairs along k
    unsigned long long w2[16];
    #pragma unroll
    for (int j = 0; j < 16; j++) {
        float w0 = W_e[(2*j    )*DC + c];
        float w1 = W_e[(2*j + 1)*DC + c];
        w2[j] = pack2(w0, w1);
    }
    const float prc = pr_sm[c];

    float acc = 0.f;
    const int sbase = sg * 64;
    for (int s0 = 0; s0 < 64; s0++) {
        const int s = sbase + s0;
        const float a = adj_sm[s];
        if (a != 0.f) {                       // warp-uniform skip (~50% of senders)
            float v = prc + psb_sm[s*DC + c];
            const ulonglong2* e2 = reinterpret_cast<const ulonglong2*>(e_sm + s*DE);
            unsigned long long acc2a = pack2(v, 0.f);
            unsigned long long acc2b = pack2(0.f, 0.f);
            #pragma unroll
            for (int j = 0; j < 8; j++) {
                ulonglong2 q = e2[j];         // LDS.128 -> 2x b64, broadcast
                acc2a = fma2(q.x, w2[2*j    ], acc2a);
                acc2b = fma2(q.y, w2[2*j + 1], acc2b);
            }
            float2 fa = unpack2(acc2a);
            float2 fb = unpack2(acc2b);
            float val = (fa.x + fb.x) + (fa.y + fb.y);
            val = (val >= 0.f) ? val : 0.01f * val;   // leaky_relu(0.01)
            acc = fmaf(a, val, acc);
        }
    }

    // --- reduce partials over the 4 sender groups ---
    red[tid] = acc;
    __syncthreads();
    if (tid < DC)
        aggsm[tid] = red[tid] + red[tid+64] + red[tid+128] + red[tid+192];
    __syncthreads();

    // --- fold edge_agg through W_n[64:128] and add to node part already in out ---
    if (tid < DO_) {
        float sum = out[(size_t)bn*DO_ + tid];
        #pragma unroll 8
        for (int cc = 0; cc < DC; cc++)
            sum = fmaf(aggsm[cc], W_n[(DN + cc)*DO_ + tid], sum);
        out[(size_t)bn*DO_ + tid] = sum;
    }
}

// ---------------------------------------------------------------------------
extern "C" void kernel_launch(void* const* d_in, const int* in_sizes, int n_in,
                              void* d_out, int out_size) {
    const float* node = (const float*)d_in[0];
    const float* edge = (const float*)d_in[1];
    const float* adjp = (const float*)d_in[2];
    const float* W_e  = (const float*)d_in[3];
    const float* b_e  = (const float*)d_in[4];
    const float* W_n  = (const float*)d_in[5];
    const float* b_n  = (const float*)d_in[6];
    float* out = (float*)d_out;

    const int smem_bytes = (N_*DE + N_*DC + N_ + DC + 256 + DC) * (int)sizeof(float); // 100,864
    cudaFuncSetAttribute(edge_kernel, cudaFuncAttributeMaxDynamicSharedMemorySize, smem_bytes);

    precompute_kernel<<<B_*N_, 64>>>(node, W_e, b_e, W_n, b_n, out);
    edge_kernel<<<B_*N_, 256, smem_bytes>>>(edge, adjp, W_e, W_n, out);
}

// round 2
// speedup vs baseline: 1.1984x; 1.1984x over previous
#include <cuda_runtime.h>

#define B_  8
#define N_  256
#define DN  64
#define DE  32
#define DC  64
#define DO_ 60

// Scratch (allocation-free rule: __device__ globals).
__device__ __align__(16) float g_pr [B_*N_*DC];
__device__ __align__(16) float g_psb[B_*N_*DC];

// ---------------------------------------------------------------------------
// Kernel A: per-node precompute.
//   g_pr [b,n,c] = node[b,n,:] @ W_e[32:96 , c]          (receiver term)
//   g_psb[b,n,c] = node[b,n,:] @ W_e[96:160, c] + b_e[c] (sender term + bias)
//   out  [b,n,o] = node[b,n,:] @ W_n[0:64 , o] + b_n[o]  (node part of output)
// ---------------------------------------------------------------------------
__global__ void precompute_kernel(const float* __restrict__ node,
                                  const float* __restrict__ W_e,
                                  const float* __restrict__ b_e,
                                  const float* __restrict__ W_n,
                                  const float* __restrict__ b_n,
                                  float* __restrict__ out) {
    __shared__ float nrow[DN];
    const int bn = blockIdx.x;
    const int c  = threadIdx.x;              // 0..63
    nrow[c] = node[bn*DN + c];
    __syncthreads();

    float accR = 0.f, accS = 0.f, accO = 0.f;
    #pragma unroll 8
    for (int k = 0; k < DN; k++) {
        float nv = nrow[k];
        accR = fmaf(nv, W_e[(DE      + k)*DC + c], accR);
        accS = fmaf(nv, W_e[(DE + DN + k)*DC + c], accS);
        if (c < DO_) accO = fmaf(nv, W_n[k*DO_ + c], accO);
    }
    g_pr [bn*DC + c] = accR;
    g_psb[bn*DC + c] = accS + b_e[c];
    if (c < DO_) out[bn*DO_ + c] = accO + b_n[c];
}

// ---------------------------------------------------------------------------
// Packed f32x2 helpers
// ---------------------------------------------------------------------------
__device__ __forceinline__ unsigned long long pack2(float a, float b) {
    unsigned long long r;
    asm("mov.b64 %0, {%1,%2};" : "=l"(r) : "f"(a), "f"(b));
    return r;
}
__device__ __forceinline__ unsigned long long fma2(unsigned long long a,
                                                   unsigned long long b,
                                                   unsigned long long c) {
    unsigned long long d;
    asm("fma.rn.f32x2 %0, %1, %2, %3;" : "=l"(d) : "l"(a), "l"(b), "l"(c));
    return d;
}
__device__ __forceinline__ float2 unpack2(unsigned long long v) {
    float2 f;
    asm("mov.b64 {%0,%1}, %2;" : "=f"(f.x), "=f"(f.y) : "l"(v));
    return f;
}

// ---------------------------------------------------------------------------
// Kernel B: one CTA per (b, r).  Branch-free inner loop over a compacted
// active-sender list (adj is exactly {0,1}).
// Thread map: c = tid&63 (channel), sg = tid>>6 (sender group of 64).
// ---------------------------------------------------------------------------
__global__ void __launch_bounds__(256, 2) edge_kernel(
    const float* __restrict__ edge_attr,
    const float* __restrict__ adj,
    const float* __restrict__ W_e,
    const float* __restrict__ W_n,
    float* __restrict__ out) {

    __shared__ __align__(16) float e_sm[N_*DE];   // 32 KB
    __shared__ int   slist[N_];                   // compacted local sender idx per group
    __shared__ int   warp_cnt[8];
    __shared__ float red[256];
    __shared__ float aggsm[DC];

    const int tid  = threadIdx.x;
    const int bn   = blockIdx.x;              // b*N + r
    const int b    = bn >> 8;
    const int c    = tid & 63;
    const int sg   = tid >> 6;                // 0..3
    const int wid  = tid >> 5;                // 0..7
    const int lane = tid & 31;

    // --- cooperative load of this receiver's edge rows (coalesced float4) ---
    const float4* esrc = reinterpret_cast<const float4*>(edge_attr) + (size_t)bn * (N_*DE/4);
    float4* e4 = reinterpret_cast<float4*>(e_sm);
    #pragma unroll
    for (int i = 0; i < (N_*DE/4)/256; i++)          // 8 iters
        e4[tid + i*256] = esrc[tid + i*256];

    // --- compaction: thread tid owns sender s = tid ---
    const float a_s = adj[(size_t)bn*N_ + tid];
    const bool  act = (a_s != 0.f);
    const unsigned m = __ballot_sync(0xffffffffu, act);
    if (lane == 0) warp_cnt[wid] = __popc(m);
    __syncthreads();
    {
        const int base = (wid & 1) ? warp_cnt[wid - 1] : 0;
        const int pos  = __popc(m & ((1u << lane) - 1u));
        if (act) slist[(wid >> 1)*64 + base + pos] = tid & 63;   // local idx in group
    }
    __syncthreads();

    const int na = warp_cnt[2*sg] + warp_cnt[2*sg + 1];

    // W_e column c (rows 0..31), packed in k-pairs
    unsigned long long w2[16];
    #pragma unroll
    for (int j = 0; j < 16; j++)
        w2[j] = pack2(W_e[(2*j)*DC + c], W_e[(2*j + 1)*DC + c]);

    const float  prc   = g_pr[(size_t)bn*DC + c];
    const float* psb_g = g_psb + (size_t)b*N_*DC + c;   // +s*DC per sender
    const int    sbase = sg * 64;
    const int*   mylist = slist + sbase;

    float acc = 0.f;
    int i = 0;
    #pragma unroll 1
    for (; i + 2 <= na; i += 2) {
        const int s0 = sbase + mylist[i];
        const int s1 = sbase + mylist[i + 1];
        const ulonglong2* e0 = reinterpret_cast<const ulonglong2*>(e_sm + s0*DE);
        const ulonglong2* e1 = reinterpret_cast<const ulonglong2*>(e_sm + s1*DE);
        const float v0 = prc + __ldg(psb_g + s0*DC);
        const float v1 = prc + __ldg(psb_g + s1*DC);
        unsigned long long a0 = pack2(v0, 0.f), b0 = 0ull;
        unsigned long long a1 = pack2(v1, 0.f), b1 = 0ull;
        #pragma unroll
        for (int j = 0; j < 8; j++) {
            ulonglong2 q0 = e0[j];
            ulonglong2 q1 = e1[j];
            a0 = fma2(q0.x, w2[2*j    ], a0);
            b0 = fma2(q0.y, w2[2*j + 1], b0);
            a1 = fma2(q1.x, w2[2*j    ], a1);
            b1 = fma2(q1.y, w2[2*j + 1], b1);
        }
        float2 fa0 = unpack2(a0), fb0 = unpack2(b0);
        float2 fa1 = unpack2(a1), fb1 = unpack2(b1);
        float val0 = (fa0.x + fb0.x) + (fa0.y + fb0.y);
        float val1 = (fa1.x + fb1.x) + (fa1.y + fb1.y);
        val0 = (val0 >= 0.f) ? val0 : 0.01f * val0;
        val1 = (val1 >= 0.f) ? val1 : 0.01f * val1;
        acc += val0 + val1;
    }
    if (i < na) {
        const int s0 = sbase + mylist[i];
        const ulonglong2* e0 = reinterpret_cast<const ulonglong2*>(e_sm + s0*DE);
        const float v0 = prc + __ldg(psb_g + s0*DC);
        unsigned long long a0 = pack2(v0, 0.f), b0 = 0ull;
        #pragma unroll
        for (int j = 0; j < 8; j++) {
            ulonglong2 q0 = e0[j];
            a0 = fma2(q0.x, w2[2*j    ], a0);
            b0 = fma2(q0.y, w2[2*j + 1], b0);
        }
        float2 fa0 = unpack2(a0), fb0 = unpack2(b0);
        float val0 = (fa0.x + fb0.x) + (fa0.y + fb0.y);
        val0 = (val0 >= 0.f) ? val0 : 0.01f * val0;
        acc += val0;
    }

    // --- reduce partials over the 4 sender groups ---
    red[tid] = acc;
    __syncthreads();
    if (tid < DC)
        aggsm[tid] = red[tid] + red[tid+64] + red[tid+128] + red[tid+192];
    __syncthreads();

    // --- fold edge_agg through W_n[64:128] and add to node part already in out ---
    if (tid < DO_) {
        float sum = out[(size_t)bn*DO_ + tid];
        #pragma unroll 8
        for (int cc = 0; cc < DC; cc++)
            sum = fmaf(aggsm[cc], W_n[(DN + cc)*DO_ + tid], sum);
        out[(size_t)bn*DO_ + tid] = sum;
    }
}

// ---------------------------------------------------------------------------
extern "C" void kernel_launch(void* const* d_in, const int* in_sizes, int n_in,
                              void* d_out, int out_size) {
    const float* node = (const float*)d_in[0];
    const float* edge = (const float*)d_in[1];
    const float* adjp = (const float*)d_in[2];
    const float* W_e  = (const float*)d_in[3];
    const float* b_e  = (const float*)d_in[4];
    const float* W_n  = (const float*)d_in[5];
    const float* b_n  = (const float*)d_in[6];
    float* out = (float*)d_out;

    precompute_kernel<<<B_*N_, 64>>>(node, W_e, b_e, W_n, b_n, out);
    edge_kernel<<<B_*N_, 256>>>(edge, adjp, W_e, W_n, out);
}

// round 4
// speedup vs baseline: 1.3834x; 1.1544x over previous
#include <cuda_runtime.h>
#include <cstdint>

#define B_  8
#define N_  256
#define DN  64
#define DE  32
#define DC  64
#define DO_ 60

// Scratch (allocation-free rule: __device__ globals).
__device__ __align__(16) float g_pr [B_*N_*DC];
__device__ __align__(16) float g_psb[B_*N_*DC];

// ---------------------------------------------------------------------------
// Kernel A: per-node precompute.
//   g_pr [b,n,c] = node[b,n,:] @ W_e[32:96 , c]
//   g_psb[b,n,c] = node[b,n,:] @ W_e[96:160, c] + b_e[c]
//   out  [b,n,o] = node[b,n,:] @ W_n[0:64 , o] + b_n[o]
// ---------------------------------------------------------------------------
__global__ void precompute_kernel(const float* __restrict__ node,
                                  const float* __restrict__ W_e,
                                  const float* __restrict__ b_e,
                                  const float* __restrict__ W_n,
                                  const float* __restrict__ b_n,
                                  float* __restrict__ out) {
    __shared__ float nrow[DN];
    const int bn = blockIdx.x;
    const int c  = threadIdx.x;              // 0..63
    nrow[c] = node[bn*DN + c];
    __syncthreads();

    float accR = 0.f, accS = 0.f, accO = 0.f;
    #pragma unroll 8
    for (int k = 0; k < DN; k++) {
        float nv = nrow[k];
        accR = fmaf(nv, W_e[(DE      + k)*DC + c], accR);
        accS = fmaf(nv, W_e[(DE + DN + k)*DC + c], accS);
        if (c < DO_) accO = fmaf(nv, W_n[k*DO_ + c], accO);
    }
    g_pr [bn*DC + c] = accR;
    g_psb[bn*DC + c] = accS + b_e[c];
    if (c < DO_) out[bn*DO_ + c] = accO + b_n[c];
}

// ---------------------------------------------------------------------------
// tf32 helpers
// ---------------------------------------------------------------------------
__device__ __forceinline__ uint32_t tf32r(float f) {
    uint32_t u;
    asm("cvt.rna.tf32.f32 %0, %1;" : "=r"(u) : "f"(f));
    return u;
}
__device__ __forceinline__ void mma_1688(float c[4],
                                         uint32_t a0, uint32_t a1, uint32_t a2, uint32_t a3,
                                         uint32_t b0, uint32_t b1) {
    asm volatile("mma.sync.aligned.m16n8k8.row.col.f32.tf32.tf32.f32 "
                 "{%0,%1,%2,%3}, {%4,%5,%6,%7}, {%8,%9}, {%0,%1,%2,%3};"
                 : "+f"(c[0]), "+f"(c[1]), "+f"(c[2]), "+f"(c[3])
                 : "r"(a0), "r"(a1), "r"(a2), "r"(a3), "r"(b0), "r"(b1));
}

#define ESTRIDE 36   // floats; (4g+t) mod 32 distinct -> conflict-free frag loads
#define WSTRIDE 68

// ---------------------------------------------------------------------------
// Kernel B: one CTA per (b, r).
//   edge_code[s,c] = lrelu(E[s,:] @ W_e[0:32,c] + pr[c] + psb[s,c])
//   agg[c] = sum_s adj[s] * edge_code[s,c];  out += agg @ W_n[64:128]
// Warp w: senders [32w, 32w+32), all 64 channels, via 64x m16n8k8 tf32 MMA.
// ---------------------------------------------------------------------------
__global__ void __launch_bounds__(256, 2) edge_kernel(
    const float* __restrict__ edge_attr,
    const float* __restrict__ adj,
    const float* __restrict__ W_e,
    const float* __restrict__ W_n,
    float* __restrict__ out) {

    __shared__ uint32_t Esm[N_*ESTRIDE];   // 36864 B (tf32 bits, padded rows)
    __shared__ uint32_t Wsm[DE*WSTRIDE];   //  8704 B
    __shared__ float red[8*DC];
    __shared__ float prsm[DC];
    __shared__ float adjsm[N_];

    const int tid  = threadIdx.x;
    const int bn   = blockIdx.x;           // b*N + r
    const int b    = bn >> 8;
    const int wid  = tid >> 5;
    const int lane = tid & 31;
    const int g    = lane >> 2;            // group id 0..7
    const int t    = lane & 3;             // thread-in-group

    // --- stage E (coalesced float4 loads, tf32-rounded, padded rows) ---
    const float4* esrc = (const float4*)edge_attr + (size_t)bn * (N_*DE/4);
    #pragma unroll
    for (int i = 0; i < 8; i++) {
        int idx = tid + i*256;             // 0..2047 float4s
        float4 e = esrc[idx];
        int row = idx >> 3, q = idx & 7;
        uint4 u = { tf32r(e.x), tf32r(e.y), tf32r(e.z), tf32r(e.w) };
        *(uint4*)&Esm[row*ESTRIDE + q*4] = u;
    }
    // --- stage W_e[0:32][64] (tf32-rounded, padded rows) ---
    #pragma unroll
    for (int i = 0; i < 8; i++) {
        int idx = tid + i*256;             // 0..2047
        Wsm[(idx >> 6)*WSTRIDE + (idx & 63)] = tf32r(W_e[idx]);
    }
    if (tid < DC)   prsm[tid] = g_pr[(size_t)bn*DC + tid];
    if (tid < N_/4) *(float4*)&adjsm[tid*4] = ((const float4*)(adj + (size_t)bn*N_))[tid];
    __syncthreads();

    // --- A fragments: 2 m-tiles x 4 k-steps x 4 regs ---
    const int s0 = wid * 32;
    uint32_t afr[2][4][4];
    #pragma unroll
    for (int mt = 0; mt < 2; mt++) {
        const int r0 = s0 + 16*mt + g;
        #pragma unroll
        for (int ks = 0; ks < 4; ks++) {
            const int k0 = 8*ks + t;
            afr[mt][ks][0] = Esm[(r0    )*ESTRIDE + k0    ];
            afr[mt][ks][1] = Esm[(r0 + 8)*ESTRIDE + k0    ];
            afr[mt][ks][2] = Esm[(r0    )*ESTRIDE + k0 + 4];
            afr[mt][ks][3] = Esm[(r0 + 8)*ESTRIDE + k0 + 4];
        }
    }

    // --- MMAs: acc[mt][nt][4] ---
    float acc[2][8][4];
    #pragma unroll
    for (int mt = 0; mt < 2; mt++)
        #pragma unroll
        for (int nt = 0; nt < 8; nt++)
            #pragma unroll
            for (int j = 0; j < 4; j++) acc[mt][nt][j] = 0.f;

    #pragma unroll
    for (int nt = 0; nt < 8; nt++) {
        uint32_t bfr[4][2];
        #pragma unroll
        for (int ks = 0; ks < 4; ks++) {
            bfr[ks][0] = Wsm[(8*ks + t    )*WSTRIDE + 8*nt + g];
            bfr[ks][1] = Wsm[(8*ks + t + 4)*WSTRIDE + 8*nt + g];
        }
        #pragma unroll
        for (int ks = 0; ks < 4; ks++) {
            mma_1688(acc[0][nt], afr[0][ks][0], afr[0][ks][1], afr[0][ks][2], afr[0][ks][3],
                     bfr[ks][0], bfr[ks][1]);
            mma_1688(acc[1][nt], afr[1][ks][0], afr[1][ks][1], afr[1][ks][2], afr[1][ks][3],
                     bfr[ks][0], bfr[ks][1]);
        }
    }

    // --- epilogue: rows owned by this lane (j = mt*2 + half) ---
    int   srow[4];
    float a1v[4], a001v[4];
    const float* prow[4];
    #pragma unroll
    for (int j = 0; j < 4; j++) {
        const int mt = j >> 1, hf = j & 1;
        srow[j]  = s0 + 16*mt + 8*hf + g;
        a1v[j]   = adjsm[srow[j]];
        a001v[j] = 0.01f * a1v[j];
        prow[j]  = g_psb + ((size_t)b*N_ + srow[j])*DC;
    }

    #pragma unroll
    for (int nt = 0; nt < 8; nt++) {
        const int c0 = 8*nt + 2*t;
        const float2 pr2 = *(const float2*)&prsm[c0];
        float ux = 0.f, uy = 0.f;
        #pragma unroll
        for (int j = 0; j < 4; j++) {
            const int mt = j >> 1, hf = j & 1;
            const float2 pb = *(const float2*)(prow[j] + c0);
            float x0 = acc[mt][nt][2*hf    ] + pr2.x + pb.x;
            float x1 = acc[mt][nt][2*hf + 1] + pr2.y + pb.y;
            ux += x0 * ((x0 >= 0.f) ? a1v[j] : a001v[j]);
            uy += x1 * ((x1 >= 0.f) ? a1v[j] : a001v[j]);
        }
        // butterfly over the 8 groups (bits 2..4 of lane)
        #pragma unroll
        for (int st = 4; st <= 16; st <<= 1) {
            ux += __shfl_xor_sync(0xffffffffu, ux, st);
            uy += __shfl_xor_sync(0xffffffffu, uy, st);
        }
        if (lane < 4) *(float2*)&red[wid*DC + c0] = make_float2(ux, uy);
    }

    __syncthreads();

    // --- combine 8 warp partials, fold through W_n[64:128] ---
    if (tid < DC) {
        float a = 0.f;
        #pragma unroll
        for (int w = 0; w < 8; w++) a += red[w*DC + tid];
        prsm[tid] = a;                       // reuse as aggsm
    }
    __syncthreads();
    if (tid < DO_) {
        float sum = out[(size_t)bn*DO_ + tid];
        #pragma unroll 8
        for (int cc = 0; cc < DC; cc++)
            sum = fmaf(prsm[cc], W_n[(DN + cc)*DO_ + tid], sum);
        out[(size_t)bn*DO_ + tid] = sum;
    }
}

// ---------------------------------------------------------------------------
extern "C" void kernel_launch(void* const* d_in, const int* in_sizes, int n_in,
                              void* d_out, int out_size) {
    const float* node = (const float*)d_in[0];
    const float* edge = (const float*)d_in[1];
    const float* adjp = (const float*)d_in[2];
    const float* W_e  = (const float*)d_in[3];
    const float* b_e  = (const float*)d_in[4];
    const float* W_n  = (const float*)d_in[5];
    const float* b_n  = (const float*)d_in[6];
    float* out = (float*)d_out;

    precompute_kernel<<<B_*N_, 64>>>(node, W_e, b_e, W_n, b_n, out);
    edge_kernel<<<B_*N_, 256>>>(edge, adjp, W_e, W_n, out);
}